// round 6
// baseline (speedup 1.0000x reference)
#include <cuda_runtime.h>
#include <float.h>

// ROI max pooling, 3-pass.
// feat: [B=8, H=50, W=50, C=256] fp32 NHWC; rois: [N,5] (img,x1,y1,x2,y2) incl.
// Dataset ROIs are 28x28 with 7x7 pooling -> each bin = aligned 4x4 window:
//   out[roi,br,bc] = max feat[img, y1+4br..+3, x1+4bc..+3].
// Pass A: Hm[b,y,x] = max_{x..x+3} feat[b,y,:]      (x: 0..46)
// Pass B: Vm[b,y,x] = max_{y..y+3} Hm[b,:,x]        (y: 0..46)
// Pass C: out[roi,br,bc] = Vm[img, y1+4br, x1+4bc]  (1 load + 1 store)
// General fallback (non-28x28 ROI): direct loop over feat.

#define FH 50
#define FW 50
#define CCH 256
#define PH 7
#define PW 7
#define HX 47               // FW - 3
#define HY 47               // FH - 3
#define NCHUNK 12           // ceil(47/4): chunks of 4 outputs

__device__ float g_hm[8 * FH * HX * CCH];   // 19.3 MB
__device__ float g_vm[8 * HY * HX * CCH];   // 18.1 MB

__device__ __forceinline__ float4 vmax2(float4 a, float4 b) {
    float4 r;
    r.x = fmaxf(a.x, b.x);
    r.y = fmaxf(a.y, b.y);
    r.z = fmaxf(a.z, b.z);
    r.w = fmaxf(a.w, b.w);
    return r;
}

// Pass A: horizontal window-4 max. One CTA = (b, y, chunk of 4 outputs).
// 7 live float4 -> no spills.
__global__ __launch_bounds__(64)
void hmax_kernel(const float* __restrict__ feat)
{
    const int id    = blockIdx.x;           // (b*FH + y)*NCHUNK + chunk
    const int chunk = id % NCHUNK;
    const int by    = id / NCHUNK;          // b*FH + y
    const int x0    = chunk * 4;
    const int coff  = threadIdx.x * 4;

    const float* rowp = feat + (size_t)by * (FW * CCH) + coff;
    float*       outp = g_hm + (size_t)by * (HX * CCH) + coff;

    float4 v[7];
    #pragma unroll
    for (int j = 0; j < 7; ++j) {
        const int x = x0 + j;
        v[j] = (x < FW) ? *reinterpret_cast<const float4*>(rowp + (size_t)x * CCH)
                        : make_float4(-FLT_MAX, -FLT_MAX, -FLT_MAX, -FLT_MAX);
    }

    float4 m01 = vmax2(v[0], v[1]);
    float4 m12 = vmax2(v[1], v[2]);
    float4 m23 = vmax2(v[2], v[3]);
    float4 m34 = vmax2(v[3], v[4]);
    float4 m45 = vmax2(v[4], v[5]);
    float4 m56 = vmax2(v[5], v[6]);

    if (x0 + 0 < HX) *reinterpret_cast<float4*>(outp + (size_t)(x0 + 0) * CCH) = vmax2(m01, m23);
    if (x0 + 1 < HX) *reinterpret_cast<float4*>(outp + (size_t)(x0 + 1) * CCH) = vmax2(m12, m34);
    if (x0 + 2 < HX) *reinterpret_cast<float4*>(outp + (size_t)(x0 + 2) * CCH) = vmax2(m23, m45);
    if (x0 + 3 < HX) *reinterpret_cast<float4*>(outp + (size_t)(x0 + 3) * CCH) = vmax2(m34, m56);
}

// Pass B: vertical window-4 max over Hm. One CTA = (b, x, y-chunk of 4).
// Same 7-load/4-output register-lean shape as Pass A; loads strided by row.
__global__ __launch_bounds__(64)
void vmax_kernel()
{
    const int id    = blockIdx.x;           // (b*HX + x)*NCHUNK + chunk
    const int chunk = id % NCHUNK;
    const int bx    = id / NCHUNK;
    const int b     = bx / HX;
    const int x     = bx - b * HX;
    const int y0    = chunk * 4;
    const int coff  = threadIdx.x * 4;

    const float* inp  = g_hm + (((size_t)b * FH) * HX + x) * CCH + coff;
    float*       outp = g_vm + (((size_t)b * HY) * HX + x) * CCH + coff;
    const size_t rstride = (size_t)HX * CCH;

    float4 v[7];
    #pragma unroll
    for (int j = 0; j < 7; ++j) {
        const int y = y0 + j;
        v[j] = (y < FH) ? *reinterpret_cast<const float4*>(inp + (size_t)y * rstride)
                        : make_float4(-FLT_MAX, -FLT_MAX, -FLT_MAX, -FLT_MAX);
    }

    float4 m01 = vmax2(v[0], v[1]);
    float4 m12 = vmax2(v[1], v[2]);
    float4 m23 = vmax2(v[2], v[3]);
    float4 m34 = vmax2(v[3], v[4]);
    float4 m45 = vmax2(v[4], v[5]);
    float4 m56 = vmax2(v[5], v[6]);

    if (y0 + 0 < HY) *reinterpret_cast<float4*>(outp + (size_t)(y0 + 0) * rstride) = vmax2(m01, m23);
    if (y0 + 1 < HY) *reinterpret_cast<float4*>(outp + (size_t)(y0 + 1) * rstride) = vmax2(m12, m34);
    if (y0 + 2 < HY) *reinterpret_cast<float4*>(outp + (size_t)(y0 + 2) * rstride) = vmax2(m23, m45);
    if (y0 + 3 < HY) *reinterpret_cast<float4*>(outp + (size_t)(y0 + 3) * rstride) = vmax2(m34, m56);
}

// Pass C: one CTA per ROI, 448 threads = 7 bc x 64 channel-slots.
// Each thread loops br 0..6: 7 independent Vm loads (MLP 7) + 7 stores,
// one rois read amortized over all of them.
__global__ __launch_bounds__(448)
void gather_kernel(const float* __restrict__ feat,
                   const int*   __restrict__ rois,
                   float*       __restrict__ out)
{
    const int roi  = blockIdx.x;
    const int t    = threadIdx.x;
    const int bc   = t >> 6;                 // 0..6
    const int coff = (t & 63) * 4;           // channel offset

    const int* r = rois + roi * 5;
    const int img = r[0];
    const int x1  = r[1];
    const int y1  = r[2];
    const int x2  = r[3];
    const int y2  = r[4];
    const int roi_h = y2 - y1 + 1;
    const int roi_w = x2 - x1 + 1;

    float* obase = out + ((size_t)(roi * PH) * PW + bc) * CCH + coff;

    if (roi_h == 28 && roi_w == 28) {
        const int xx = x1 + 4 * bc;
        const float* p = g_vm
            + (((size_t)img * HY + y1) * HX + xx) * CCH + coff;
        const size_t brstride = 4 * (size_t)HX * CCH;   // +4 rows per br

        float4 v[PH];
        #pragma unroll
        for (int br = 0; br < PH; ++br)
            v[br] = *reinterpret_cast<const float4*>(p + (size_t)br * brstride);
        #pragma unroll
        for (int br = 0; br < PH; ++br)
            *reinterpret_cast<float4*>(obase + (size_t)(br * PW) * CCH) = v[br];
    } else {
        // General fallback: direct max over each bin's pixel range in feat.
        const int cs = (bc * roi_w + PW - 1) / PW;
        const int ce = (bc == PW - 1) ? roi_w : ((bc + 1) * roi_w + PW - 1) / PW;
        const float* base = feat
            + (((size_t)img * FH + (size_t)y1) * FW + (size_t)x1) * CCH + coff;
        for (int br = 0; br < PH; ++br) {
            const int rs = (br * roi_h + PH - 1) / PH;
            const int re = (br == PH - 1) ? roi_h
                                          : ((br + 1) * roi_h + PH - 1) / PH;
            float4 m = make_float4(-FLT_MAX, -FLT_MAX, -FLT_MAX, -FLT_MAX);
            for (int y = rs; y < re; ++y) {
                const float* rowp = base + (size_t)y * (FW * CCH);
                for (int x = cs; x < ce; ++x) {
                    const float4 v = *reinterpret_cast<const float4*>(rowp + (size_t)x * CCH);
                    m.x = fmaxf(m.x, v.x); m.y = fmaxf(m.y, v.y);
                    m.z = fmaxf(m.z, v.z); m.w = fmaxf(m.w, v.w);
                }
            }
            *reinterpret_cast<float4*>(obase + (size_t)(br * PW) * CCH) = m;
        }
    }
}

extern "C" void kernel_launch(void* const* d_in, const int* in_sizes, int n_in,
                              void* d_out, int out_size)
{
    const float* feat = (const float*)d_in[0];
    const int*   rois = (const int*)d_in[1];
    const int n_rois = in_sizes[1] / 5;
    float* out = (float*)d_out;

    hmax_kernel<<<8 * FH * NCHUNK, 64>>>(feat);
    vmax_kernel<<<8 * HX * NCHUNK, 64>>>();
    gather_kernel<<<n_rois, 448>>>(feat, rois, out);
}

// round 7
// speedup vs baseline: 1.2937x; 1.2937x over previous
#include <cuda_runtime.h>
#include <float.h>

// ROI max pooling, 2-pass (fused pyramid + trivial gather).
// feat: [B=8, H=50, W=50, C=256] fp32 NHWC; rois: [N,5] (img,x1,y1,x2,y2) incl.
// Dataset ROIs are 28x28 with 7x7 pooling -> each bin = aligned 4x4 window:
//   out[roi,br,bc] = max feat[img, y1+4br..+3, x1+4bc..+3].
// Pass A (fused): Vm[b,y,x] = max_{4x4 window} feat[b, y..y+3, x..x+3]
//   computed directly: per input row, horizontal 4-max staged in
//   thread-private smem; then vertical 4-max over the 7 staged rows.
// Pass B: out[roi,br,bc] = Vm[img, y1+4br, x1+4bc]  (1 load + 1 store)
// General fallback (non-28x28 ROI): direct loop over feat.

#define FH 50
#define FW 50
#define CCH 256
#define PH 7
#define PW 7
#define HX 47               // FW - 3 (valid window origins)
#define HY 47
#define TW 4                // Vm tile width per CTA
#define TH 4                // Vm tile height per CTA
#define NXC 12              // ceil(47/4)
#define NYC 12

__device__ float g_vm[8 * HY * HX * CCH];   // 18.1 MB

__device__ __forceinline__ float4 vmax2(float4 a, float4 b) {
    float4 r;
    r.x = fmaxf(a.x, b.x);
    r.y = fmaxf(a.y, b.y);
    r.z = fmaxf(a.z, b.z);
    r.w = fmaxf(a.w, b.w);
    return r;
}

// Fused H+V window-4 max: one CTA = (b, 4x4 output tile), 64 threads x 4ch.
// Thread-private smem staging (no __syncthreads needed).
__global__ __launch_bounds__(64)
void hvmax_kernel(const float* __restrict__ feat)
{
    __shared__ float4 hs[7][TW][64];        // [in-row][out-col][thread] = 28 KB

    const int id = blockIdx.x;              // ((b*NYC)+yc)*NXC + xc
    const int xc = id % NXC;
    const int t1 = id / NXC;
    const int yc = t1 % NYC;
    const int b  = t1 / NYC;
    const int x0 = xc * TW;
    const int y0 = yc * TH;
    const int tid  = threadIdx.x;
    const int coff = tid * 4;

    const float4 NEG = make_float4(-FLT_MAX, -FLT_MAX, -FLT_MAX, -FLT_MAX);

    // Phase 1: per input row, 7 loads -> 4 horizontal window maxes -> smem.
    #pragma unroll
    for (int j = 0; j < 7; ++j) {
        const int y = y0 + j;
        float4 v[7];
        if (y < FH) {
            const float* rowp = feat + ((size_t)(b * FH + y) * FW) * CCH + coff;
            #pragma unroll
            for (int k = 0; k < 7; ++k) {
                const int x = x0 + k;
                v[k] = (x < FW)
                     ? *reinterpret_cast<const float4*>(rowp + (size_t)x * CCH)
                     : NEG;
            }
        } else {
            #pragma unroll
            for (int k = 0; k < 7; ++k) v[k] = NEG;
        }
        const float4 m01 = vmax2(v[0], v[1]);
        const float4 m23 = vmax2(v[2], v[3]);
        const float4 m12 = vmax2(v[1], v[2]);
        const float4 m34 = vmax2(v[3], v[4]);
        const float4 m45 = vmax2(v[4], v[5]);
        const float4 m56 = vmax2(v[5], v[6]);
        hs[j][0][tid] = vmax2(m01, m23);
        hs[j][1][tid] = vmax2(m12, m34);
        hs[j][2][tid] = vmax2(m23, m45);
        hs[j][3][tid] = vmax2(m34, m56);
    }

    // Phase 2: vertical window-4 max over staged rows (own slots only).
    #pragma unroll
    for (int r = 0; r < TH; ++r) {
        const int yo = y0 + r;
        if (yo >= HY) continue;
        float* outp = g_vm + (((size_t)b * HY + yo) * HX) * CCH + coff;
        #pragma unroll
        for (int c = 0; c < TW; ++c) {
            const int xo = x0 + c;
            if (xo >= HX) continue;
            const float4 m = vmax2(vmax2(hs[r][c][tid],     hs[r + 1][c][tid]),
                                   vmax2(hs[r + 2][c][tid], hs[r + 3][c][tid]));
            *reinterpret_cast<float4*>(outp + (size_t)xo * CCH) = m;
        }
    }
}

// Gather: one CTA per ROI, 448 threads = 7 bc x 64 channel-slots.
// Each thread loops br 0..6: 7 independent Vm loads (MLP 7) + 7 stores.
__global__ __launch_bounds__(448)
void gather_kernel(const float* __restrict__ feat,
                   const int*   __restrict__ rois,
                   float*       __restrict__ out)
{
    const int roi  = blockIdx.x;
    const int t    = threadIdx.x;
    const int bc   = t >> 6;                 // 0..6
    const int coff = (t & 63) * 4;           // channel offset

    const int* r = rois + roi * 5;
    const int img = r[0];
    const int x1  = r[1];
    const int y1  = r[2];
    const int x2  = r[3];
    const int y2  = r[4];
    const int roi_h = y2 - y1 + 1;
    const int roi_w = x2 - x1 + 1;

    float* obase = out + ((size_t)(roi * PH) * PW + bc) * CCH + coff;

    if (roi_h == 28 && roi_w == 28) {
        const int xx = x1 + 4 * bc;
        const float* p = g_vm
            + (((size_t)img * HY + y1) * HX + xx) * CCH + coff;
        const size_t brstride = 4 * (size_t)HX * CCH;   // +4 rows per br

        float4 v[PH];
        #pragma unroll
        for (int br = 0; br < PH; ++br)
            v[br] = *reinterpret_cast<const float4*>(p + (size_t)br * brstride);
        #pragma unroll
        for (int br = 0; br < PH; ++br)
            *reinterpret_cast<float4*>(obase + (size_t)(br * PW) * CCH) = v[br];
    } else {
        // General fallback: direct max over each bin's pixel range in feat.
        const int cs = (bc * roi_w + PW - 1) / PW;
        const int ce = (bc == PW - 1) ? roi_w : ((bc + 1) * roi_w + PW - 1) / PW;
        const float* base = feat
            + (((size_t)img * FH + (size_t)y1) * FW + (size_t)x1) * CCH + coff;
        for (int br = 0; br < PH; ++br) {
            const int rs = (br * roi_h + PH - 1) / PH;
            const int re = (br == PH - 1) ? roi_h
                                          : ((br + 1) * roi_h + PH - 1) / PH;
            float4 m = make_float4(-FLT_MAX, -FLT_MAX, -FLT_MAX, -FLT_MAX);
            for (int y = rs; y < re; ++y) {
                const float* rowp = base + (size_t)y * (FW * CCH);
                for (int x = cs; x < ce; ++x) {
                    const float4 v = *reinterpret_cast<const float4*>(rowp + (size_t)x * CCH);
                    m.x = fmaxf(m.x, v.x); m.y = fmaxf(m.y, v.y);
                    m.z = fmaxf(m.z, v.z); m.w = fmaxf(m.w, v.w);
                }
            }
            *reinterpret_cast<float4*>(obase + (size_t)(br * PW) * CCH) = m;
        }
    }
}

extern "C" void kernel_launch(void* const* d_in, const int* in_sizes, int n_in,
                              void* d_out, int out_size)
{
    const float* feat = (const float*)d_in[0];
    const int*   rois = (const int*)d_in[1];
    const int n_rois = in_sizes[1] / 5;
    float* out = (float*)d_out;

    hvmax_kernel<<<8 * NYC * NXC, 64>>>(feat);
    gather_kernel<<<n_rois, 448>>>(feat, rois, out);
}